// round 9
// baseline (speedup 1.0000x reference)
#include <cuda_runtime.h>
#include <math_constants.h>
#include <cstdint>

// Problem constants (fixed shapes from the reference)
constexpr int kB = 2;
constexpr int kC = 32;
constexpr int kH = 32;
constexpr int kW = 256;
constexpr int kN = kH * kW;            // 8192 points per batch
constexpr int kNX = 440;
constexpr int kNY = 500;
constexpr int kNVOX = kNX * kNY;       // 220000
constexpr float PCR0 = 0.0f, PCR1 = -40.0f, PCR2 = -3.0f, PCR5 = 1.0f;
constexpr float VOXS = 0.16f;

constexpr int TILE = 2048;             // candidates per smem tile (32 KB)
constexpr int NNB_PER_B = 512;         // NN blocks per batch (16 far pts each)

// Scratch (allocation-free: __device__ globals; zero-initialized at load).
// INVARIANT: g_sum all-zero at kernel_launch entry (k_fin restores);
//            g_cnt zeroed by k_init each call.
__device__ __align__(16) float g_sum[kB * kC * kNVOX];  // 56.3 MB persistent
__device__ __align__(16) float g_cnt[kB * kNVOX];
__device__ float4 g_near[kB * kN];     // compacted near pts: x,y,z, bitcast(idx)
__device__ float4 g_far [kB * kN];     // compacted far pts
__device__ int    g_ncnt[kB];
__device__ int    g_fcnt[kB];

// ---------------------------------------------------------------------------
// 1) k_init: blocks 0..3 compact (batch x near/far) via smem staging with a
//    fully-unrolled high-MLP emit; blocks 4.. zero g_cnt (1.76 MB).
// ---------------------------------------------------------------------------
__global__ void __launch_bounds__(1024) k_init(const float* __restrict__ pts,
                                               const float* __restrict__ ptsf,
                                               const int* __restrict__ m,
                                               const int* __restrict__ mf) {
    if (blockIdx.x >= 4) {
        const int ctotal = (kB * kNVOX) / 4;       // 110,000 float4
        const float4 z = make_float4(0.f, 0.f, 0.f, 0.f);
        int i = (blockIdx.x - 4) * 1024 + threadIdx.x;
        if (i < ctotal) reinterpret_cast<float4*>(g_cnt)[i] = z;
        return;
    }

    // ---- compaction: one block per (batch, near/far) ----
    __shared__ int s_idx[kN];  // 32 KB: ordered valid source indices
    __shared__ int wsum[32];

    const int b   = blockIdx.x >> 1;
    const bool fr = blockIdx.x & 1;
    const float* p  = (fr ? ptsf : pts) + (size_t)b * 4 * kN;
    const int*   mm = (fr ? mf : m) + (size_t)b * kN;
    float4* dst     = (fr ? g_far : g_near) + (size_t)b * kN;
    int* cnt_out    = fr ? &g_fcnt[b] : &g_ncnt[b];

    const int t = threadIdx.x;
    const int lane = t & 31, w = t >> 5;
    constexpr int PER = kN / 1024;  // 8

    int msk[PER];
    int c = 0;
#pragma unroll
    for (int k = 0; k < PER; ++k) { msk[k] = mm[t * PER + k]; c += (msk[k] > 0); }

    // two-level exclusive scan
    int inc = c;
#pragma unroll
    for (int off = 1; off < 32; off <<= 1) {
        int n = __shfl_up_sync(0xFFFFFFFFu, inc, off);
        if (lane >= off) inc += n;
    }
    if (lane == 31) wsum[w] = inc;
    __syncthreads();
    if (t < 32) {
        int v = wsum[t];
        int p2 = v;
#pragma unroll
        for (int off = 1; off < 32; off <<= 1) {
            int n = __shfl_up_sync(0xFFFFFFFFu, p2, off);
            if (t >= off) p2 += n;
        }
        wsum[t] = p2 - v;
        if (t == 31) *cnt_out = p2;
    }
    __syncthreads();
    int off = wsum[w] + inc - c;

#pragma unroll
    for (int k = 0; k < PER; ++k)
        if (msk[k] > 0) s_idx[off++] = t * PER + k;
    __syncthreads();

    // phase 2: cooperative emit, fully unrolled (all gathers in flight)
    int cnt = *cnt_out;
    int j = t;
#pragma unroll
    for (int k = 0; k < PER; ++k) {
        if (j < cnt) {
            int n = s_idx[j];
            dst[j] = make_float4(p[n], p[kN + n], p[2 * kN + n],
                                 __int_as_float(n));
        }
        j += 1024;
    }
}

// ---------------------------------------------------------------------------
// 2) k_main
//    Blocks [0, kB*NNB_PER_B): 3-NN + interp + atomic scatter into g_sum.
//    Blocks [kB*NNB_PER_B, +64): near-point scatter into g_sum.
// ---------------------------------------------------------------------------
__device__ __forceinline__ void insert3v(float dd, int v,
                                         float& l0, float& l1, float& l2,
                                         int& v0, int& v1, int& v2) {
    if (dd < l2) {
        if (dd < l1) {
            l2 = l1; v2 = v1;
            if (dd < l0) { l1 = l0; v1 = v0; l0 = dd; v0 = v; }
            else         { l1 = dd; v1 = v; }
        } else { l2 = dd; v2 = v; }
    }
}

__device__ __forceinline__ float warpmin(float x) {
#pragma unroll
    for (int off = 16; off > 0; off >>= 1)
        x = fminf(x, __shfl_xor_sync(0xFFFFFFFFu, x, off));
    return x;
}

// merge 32 lane-local sorted triples -> warp top-3 (ties by lower idx)
__device__ __forceinline__ void merge32(float l0, float l1, float l2,
                                        int v0, int v1, int v2,
                                        float rd[3], int ri[3]) {
    int pos = 0;
#pragma unroll
    for (int k = 0; k < 3; ++k) {
        float h  = (pos == 0) ? l0 : (pos == 1) ? l1 : (pos == 2) ? l2 : CUDART_INF_F;
        int   hi = (pos == 0) ? v0 : (pos == 1) ? v1 : (pos == 2) ? v2 : 0x7FFFFFFF;
        float mh = h; int mi = hi;
#pragma unroll
        for (int off = 16; off > 0; off >>= 1) {
            float oh = __shfl_xor_sync(0xFFFFFFFFu, mh, off);
            int   oi = __shfl_xor_sync(0xFFFFFFFFu, mi, off);
            if (oh < mh || (oh == mh && oi < mi)) { mh = oh; mi = oi; }
        }
        rd[k] = mh; ri[k] = mi;
        if (h == mh && hi == mi) ++pos;
    }
}

__global__ void __launch_bounds__(256) k_main(const float* __restrict__ fv,
                                              const float* __restrict__ pts,
                                              const int* __restrict__ m) {
    // ---- role: near-point scatter ----
    if (blockIdx.x >= kB * NNB_PER_B) {
        int idx = (blockIdx.x - kB * NNB_PER_B) * 256 + threadIdx.x;
        if (idx >= kB * kN) return;
        int b = idx / kN, n = idx % kN;
        if (m[(size_t)b * kN + n] <= 0) return;
        const float* p = pts + (size_t)b * 4 * kN;
        float x = p[n], y = p[kN + n], z = p[2 * kN + n];
        int ix = (int)floorf((x - PCR0) / VOXS);
        int iy = (int)floorf((y - PCR1) / VOXS);
        if (ix < 0 || ix >= kNX || iy < 0 || iy >= kNY || z < PCR2 || z >= PCR5)
            return;
        int seg = iy * kNX + ix;
        float* ob = g_sum + (size_t)b * kC * kNVOX + seg;
        const float* f = fv + (size_t)b * kC * kN + n;
#pragma unroll
        for (int c = 0; c < kC; ++c)
            atomicAdd(ob + (size_t)c * kNVOX, f[(size_t)c * kN]);
        atomicAdd(&g_cnt[(size_t)b * kNVOX + seg], 1.0f);
        return;
    }

    // ---- role: 3-NN ----
    __shared__ float4 sp[TILE];

    const int b    = blockIdx.x / NNB_PER_B;
    const int fb   = blockIdx.x % NNB_PER_B;
    const int base = fb * 16;
    const int fcnt = g_fcnt[b];
    if (base >= fcnt) return;                    // uniform block exit

    const int lane = threadIdx.x & 31;
    const int w    = threadIdx.x >> 5;
    const int rA   = base + 2 * w;
    const int rB   = rA + 1;
    const bool activeA = (rA < fcnt);
    const bool activeB = (rB < fcnt);

    float4 fpA = g_far[(size_t)b * kN + (activeA ? rA : 0)];
    float4 fpB = g_far[(size_t)b * kN + (activeB ? rB : 0)];
    const float aX = -2.0f * fpA.x, aY = -2.0f * fpA.y, aZ = -2.0f * fpA.z;
    const float bX = -2.0f * fpB.x, bY = -2.0f * fpB.y, bZ = -2.0f * fpB.z;

    const int V = g_ncnt[b];
    const float4* __restrict__ vp = &g_near[(size_t)b * kN];

    float lA0 = CUDART_INF_F, lA1 = CUDART_INF_F, lA2 = CUDART_INF_F;
    int   vA0 = 0x7FFFFFFF,   vA1 = 0x7FFFFFFF,   vA2 = 0x7FFFFFFF;
    float lB0 = CUDART_INF_F, lB1 = CUDART_INF_F, lB2 = CUDART_INF_F;
    int   vB0 = 0x7FFFFFFF,   vB1 = 0x7FFFFFFF,   vB2 = 0x7FFFFFFF;
    float TmA = activeA ? CUDART_INF_F : -CUDART_INF_F;
    float TmB = activeB ? CUDART_INF_F : -CUDART_INF_F;

    int it = 0;
    for (int start = 0; start < V; start += TILE) {
        int len = V - start; len = (len > TILE) ? TILE : len;
        int Lpad = (len + 127) & ~127;
        for (int i = threadIdx.x; i < Lpad; i += 256) {
            float4 p;
            if (i < len) {
                p = vp[start + i];
                p.w = fmaf(p.x, p.x, fmaf(p.y, p.y, p.z * p.z));
            } else {
                p = make_float4(0.f, 0.f, 0.f, CUDART_INF_F);
            }
            sp[i] = p;
        }
        __syncthreads();

        for (int k = 0; k < Lpad; k += 128, ++it) {
            float4 p0 = sp[k + lane];
            float4 p1 = sp[k + lane + 32];
            float4 p2 = sp[k + lane + 64];
            float4 p3 = sp[k + lane + 96];
            float a0 = fmaf(p0.x, aX, fmaf(p0.y, aY, fmaf(p0.z, aZ, p0.w)));
            float a1 = fmaf(p1.x, aX, fmaf(p1.y, aY, fmaf(p1.z, aZ, p1.w)));
            float a2 = fmaf(p2.x, aX, fmaf(p2.y, aY, fmaf(p2.z, aZ, p2.w)));
            float a3 = fmaf(p3.x, aX, fmaf(p3.y, aY, fmaf(p3.z, aZ, p3.w)));
            float b0 = fmaf(p0.x, bX, fmaf(p0.y, bY, fmaf(p0.z, bZ, p0.w)));
            float b1 = fmaf(p1.x, bX, fmaf(p1.y, bY, fmaf(p1.z, bZ, p1.w)));
            float b2 = fmaf(p2.x, bX, fmaf(p2.y, bY, fmaf(p2.z, bZ, p2.w)));
            float b3 = fmaf(p3.x, bX, fmaf(p3.y, bY, fmaf(p3.z, bZ, p3.w)));
            float mnA = fminf(fminf(a0, a1), fminf(a2, a3));
            float mnB = fminf(fminf(b0, b1), fminf(b2, b3));
            int ci = start + k + lane;
            if (mnA < TmA) {
                insert3v(a0, ci,      lA0, lA1, lA2, vA0, vA1, vA2);
                insert3v(a1, ci + 32, lA0, lA1, lA2, vA0, vA1, vA2);
                insert3v(a2, ci + 64, lA0, lA1, lA2, vA0, vA1, vA2);
                insert3v(a3, ci + 96, lA0, lA1, lA2, vA0, vA1, vA2);
            }
            if (mnB < TmB) {
                insert3v(b0, ci,      lB0, lB1, lB2, vB0, vB1, vB2);
                insert3v(b1, ci + 32, lB0, lB1, lB2, vB0, vB1, vB2);
                insert3v(b2, ci + 64, lB0, lB1, lB2, vB0, vB1, vB2);
                insert3v(b3, ci + 96, lB0, lB1, lB2, vB0, vB1, vB2);
            }
            if ((it & 3) == 3) {  // refresh conservative thresholds (stale=safe)
                if (activeA) TmA = warpmin(lA2);
                if (activeB) TmB = warpmin(lB2);
            }
        }
        __syncthreads();
    }

    float rdA[3], rdB[3];
    int riA[3], riB[3];
    merge32(lA0, lA1, lA2, vA0, vA1, vA2, rdA, riA);
    merge32(lB0, lB1, lB2, vB0, vB1, vB2, rdB, riB);

    const bool isA = lane < 16;
    const int lh = lane & 15;
    const bool act = isA ? activeA : activeB;
    if (!act) return;

    float fx = isA ? fpA.x : fpB.x;
    float fy = isA ? fpA.y : fpB.y;
    float fz = isA ? fpA.z : fpB.z;

    float rd[3];
    int u[3];
#pragma unroll
    for (int k = 0; k < 3; ++k) {
        int r = isA ? riA[k] : riB[k];
        if ((unsigned)r < (unsigned)kN) {
            float4 p = vp[r];
            float dx = p.x - fx, dy = p.y - fy, dz = p.z - fz;
            rd[k] = fmaf(dx, dx, fmaf(dy, dy, dz * dz));
            u[k] = __float_as_int(p.w);
        } else {
            rd[k] = CUDART_INF_F;
            u[k] = 0;
        }
    }

    float w0 = 1.0f / (rd[0] + 1e-8f);
    float w1 = 1.0f / (rd[1] + 1e-8f);
    float w2 = 1.0f / (rd[2] + 1e-8f);
    float ws = w0 + w1 + w2;
    w0 /= ws; w1 /= ws; w2 /= ws;

    int ix = (int)floorf((fx - PCR0) / VOXS);
    int iy = (int)floorf((fy - PCR1) / VOXS);
    bool inb = ix >= 0 && ix < kNX && iy >= 0 && iy < kNY &&
               fz >= PCR2 && fz < PCR5;
    if (!inb) return;
    int seg = iy * kNX + ix;

    const float* fb_ = fv + (size_t)b * kC * kN;
    float* ob = g_sum + (size_t)b * kC * kNVOX;
#pragma unroll
    for (int k = 0; k < 2; ++k) {
        int c = lh + 16 * k;
        const float* fc = fb_ + (size_t)c * kN;
        float val = w0 * fc[u[0]] + w1 * fc[u[1]] + w2 * fc[u[2]];
        atomicAdd(ob + (size_t)c * kNVOX + seg, val);
    }
    if (lh == 0) atomicAdd(&g_cnt[(size_t)b * kNVOX + seg], 1.0f);
}

// ---------------------------------------------------------------------------
// 3) k_fin: sole writer of out (dense). out = cnt>0 ? sum/max(cnt,1) : 0.
//    Zeroes the g_sum entries it consumed (restores cross-replay invariant).
// ---------------------------------------------------------------------------
__global__ void __launch_bounds__(256) k_fin(float4* __restrict__ out) {
    constexpr int perC = kNVOX / 4;                  // 55000 float4 per channel
    int i4 = blockIdx.x * 256 + threadIdx.x;
    if (i4 >= kB * kC * perC) return;
    int v4 = i4 % perC;
    int b  = i4 / (kC * perC);

    float4 cnt = reinterpret_cast<const float4*>(g_cnt)[b * perC + v4];
    float4 o = make_float4(0.f, 0.f, 0.f, 0.f);
    if ((cnt.x + cnt.y + cnt.z + cnt.w) > 0.0f) {
        float4* sp = reinterpret_cast<float4*>(g_sum) + i4;
        float4 s = *sp;
        o.x = s.x / fmaxf(cnt.x, 1.0f);
        o.y = s.y / fmaxf(cnt.y, 1.0f);
        o.z = s.z / fmaxf(cnt.z, 1.0f);
        o.w = s.w / fmaxf(cnt.w, 1.0f);
        *sp = make_float4(0.f, 0.f, 0.f, 0.f);
    }
    out[i4] = o;
}

// ---------------------------------------------------------------------------
extern "C" void kernel_launch(void* const* d_in, const int* in_sizes, int n_in,
                              void* d_out, int out_size) {
    const float* fv   = (const float*)d_in[0];  // (B,C,H,W)
    const float* pts  = (const float*)d_in[1];  // (B,4,H,W)
    const float* ptsf = (const float*)d_in[2];  // (B,4,H,W)
    const int*   m    = (const int*)d_in[3];    // (B,H,W)
    const int*   mf   = (const int*)d_in[4];    // (B,H,W)
    float* out = (float*)d_out;                 // (B,C,NY,NX)

    k_init<<<4 + 108, 1024>>>(pts, ptsf, m, mf);
    k_main<<<kB * NNB_PER_B + (kB * kN) / 256, 256>>>(fv, pts, m);
    k_fin<<<(kB * kC * (kNVOX / 4) + 255) / 256, 256>>>((float4*)out);
}

// round 10
// speedup vs baseline: 1.3429x; 1.3429x over previous
#include <cuda_runtime.h>
#include <math_constants.h>
#include <cstdint>

// Problem constants (fixed shapes from the reference)
constexpr int kB = 2;
constexpr int kC = 32;
constexpr int kH = 32;
constexpr int kW = 256;
constexpr int kN = kH * kW;            // 8192 points per batch
constexpr int kNX = 440;
constexpr int kNY = 500;
constexpr int kNVOX = kNX * kNY;       // 220000
constexpr float PCR0 = 0.0f, PCR1 = -40.0f, PCR2 = -3.0f, PCR5 = 1.0f;
constexpr float VOXS = 0.16f;

constexpr int TILE  = 2048;            // candidates per smem tile
constexpr int PAIRS = TILE / 2;        // packed candidate pairs per tile
constexpr int NNB_PER_B = 512;         // NN blocks per batch (16 far pts each)
constexpr int ZB = 1020;               // zero blocks in k_init

// Scratch (allocation-free: __device__ globals)
__device__ __align__(16) float g_cnt[kB * kNVOX];
__device__ float4 g_near[kB * kN];     // compacted near pts: x,y,z, bitcast(idx)
__device__ float4 g_far [kB * kN];     // compacted far pts
__device__ int    g_ncnt[kB];
__device__ int    g_fcnt[kB];

// ---- packed f32x2 helpers (sm_103a FFMA2 only reachable via PTX) ----------
__device__ __forceinline__ unsigned long long fma2(unsigned long long a,
                                                   unsigned long long b,
                                                   unsigned long long c) {
    unsigned long long d;
    asm("fma.rn.f32x2 %0, %1, %2, %3;" : "=l"(d) : "l"(a), "l"(b), "l"(c));
    return d;
}
__device__ __forceinline__ unsigned long long pack2(float lo, float hi) {
    unsigned long long r;
    asm("mov.b64 %0, {%1, %2};" : "=l"(r) : "f"(lo), "f"(hi));
    return r;
}
__device__ __forceinline__ void unpack2(unsigned long long v,
                                        float& lo, float& hi) {
    asm("mov.b64 {%0, %1}, %2;" : "=f"(lo), "=f"(hi) : "l"(v));
}

// ---------------------------------------------------------------------------
// 1) k_init: blocks 0..3 compact (batch x near/far) via smem staging;
//    blocks 4.. zero out (56 MB) + g_cnt. Zero work hides compact latency.
// ---------------------------------------------------------------------------
__global__ void __launch_bounds__(1024) k_init(float4* __restrict__ out4,
                                               const float* __restrict__ pts,
                                               const float* __restrict__ ptsf,
                                               const int* __restrict__ m,
                                               const int* __restrict__ mf) {
    if (blockIdx.x >= 4) {
        const int total  = (kB * kC * kNVOX) / 4;  // 3,520,000 float4
        const int ctotal = (kB * kNVOX) / 4;       //   110,000 float4
        const float4 z = make_float4(0.f, 0.f, 0.f, 0.f);
        for (int i = (blockIdx.x - 4) * 1024 + threadIdx.x; i < total + ctotal;
             i += ZB * 1024) {
            if (i < total) out4[i] = z;
            else           reinterpret_cast<float4*>(g_cnt)[i - total] = z;
        }
        return;
    }

    // ---- compaction: one block per (batch, near/far) ----
    __shared__ int s_idx[kN];  // 32 KB: ordered valid source indices
    __shared__ int wsum[32];
    __shared__ int s_total;

    const int b   = blockIdx.x >> 1;
    const bool fr = blockIdx.x & 1;
    const float* p  = (fr ? ptsf : pts) + (size_t)b * 4 * kN;
    const int*   mm = (fr ? mf : m) + (size_t)b * kN;
    float4* dst     = (fr ? g_far : g_near) + (size_t)b * kN;
    int* cnt_out    = fr ? &g_fcnt[b] : &g_ncnt[b];

    const int t = threadIdx.x;
    const int lane = t & 31, w = t >> 5;
    constexpr int PER = kN / 1024;  // 8

    int4 mv0 = reinterpret_cast<const int4*>(mm)[t * 2];
    int4 mv1 = reinterpret_cast<const int4*>(mm)[t * 2 + 1];
    int msk[PER] = {mv0.x, mv0.y, mv0.z, mv0.w, mv1.x, mv1.y, mv1.z, mv1.w};
    int c = 0;
#pragma unroll
    for (int k = 0; k < PER; ++k) c += (msk[k] > 0);

    // two-level exclusive scan
    int inc = c;
#pragma unroll
    for (int off = 1; off < 32; off <<= 1) {
        int n = __shfl_up_sync(0xFFFFFFFFu, inc, off);
        if (lane >= off) inc += n;
    }
    if (lane == 31) wsum[w] = inc;
    __syncthreads();
    if (t < 32) {
        int v = wsum[t];
        int p2 = v;
#pragma unroll
        for (int off = 1; off < 32; off <<= 1) {
            int n = __shfl_up_sync(0xFFFFFFFFu, p2, off);
            if (t >= off) p2 += n;
        }
        wsum[t] = p2 - v;
        if (t == 31) { *cnt_out = p2; s_total = p2; }
    }
    __syncthreads();
    int off = wsum[w] + inc - c;

#pragma unroll
    for (int k = 0; k < PER; ++k)
        if (msk[k] > 0) s_idx[off++] = t * PER + k;
    __syncthreads();

    // phase 2: cooperative emit, fully unrolled (all gathers in flight)
    int cnt = s_total;
    int j = t;
#pragma unroll
    for (int k = 0; k < PER; ++k) {
        if (j < cnt) {
            int n = s_idx[j];
            dst[j] = make_float4(p[n], p[kN + n], p[2 * kN + n],
                                 __int_as_float(n));
        }
        j += 1024;
    }
}

// ---------------------------------------------------------------------------
// 2) k_main: NN blocks + near-scatter blocks; atomics straight into out.
// ---------------------------------------------------------------------------
__device__ __forceinline__ void insert3v(float dd, int v,
                                         float& l0, float& l1, float& l2,
                                         int& v0, int& v1, int& v2) {
    if (dd < l2) {
        if (dd < l1) {
            l2 = l1; v2 = v1;
            if (dd < l0) { l1 = l0; v1 = v0; l0 = dd; v0 = v; }
            else         { l1 = dd; v1 = v; }
        } else { l2 = dd; v2 = v; }
    }
}

__device__ __forceinline__ float warpmin(float x) {
#pragma unroll
    for (int off = 16; off > 0; off >>= 1)
        x = fminf(x, __shfl_xor_sync(0xFFFFFFFFu, x, off));
    return x;
}

// merge 32 lane-local sorted triples -> warp top-3 (ties by lower idx)
__device__ __forceinline__ void merge32(float l0, float l1, float l2,
                                        int v0, int v1, int v2,
                                        float rd[3], int ri[3]) {
    int pos = 0;
#pragma unroll
    for (int k = 0; k < 3; ++k) {
        float h  = (pos == 0) ? l0 : (pos == 1) ? l1 : (pos == 2) ? l2 : CUDART_INF_F;
        int   hi = (pos == 0) ? v0 : (pos == 1) ? v1 : (pos == 2) ? v2 : 0x7FFFFFFF;
        float mh = h; int mi = hi;
#pragma unroll
        for (int off = 16; off > 0; off >>= 1) {
            float oh = __shfl_xor_sync(0xFFFFFFFFu, mh, off);
            int   oi = __shfl_xor_sync(0xFFFFFFFFu, mi, off);
            if (oh < mh || (oh == mh && oi < mi)) { mh = oh; mi = oi; }
        }
        rd[k] = mh; ri[k] = mi;
        if (h == mh && hi == mi) ++pos;
    }
}

__global__ void __launch_bounds__(256) k_main(const float* __restrict__ fv,
                                              const float* __restrict__ pts,
                                              const int* __restrict__ m,
                                              float* __restrict__ out) {
    // ---- role: near-point scatter ----
    if (blockIdx.x >= kB * NNB_PER_B) {
        int idx = (blockIdx.x - kB * NNB_PER_B) * 256 + threadIdx.x;
        if (idx >= kB * kN) return;
        int b = idx / kN, n = idx % kN;
        if (m[(size_t)b * kN + n] <= 0) return;
        const float* p = pts + (size_t)b * 4 * kN;
        float x = p[n], y = p[kN + n], z = p[2 * kN + n];
        int ix = (int)floorf((x - PCR0) / VOXS);
        int iy = (int)floorf((y - PCR1) / VOXS);
        if (ix < 0 || ix >= kNX || iy < 0 || iy >= kNY || z < PCR2 || z >= PCR5)
            return;
        int seg = iy * kNX + ix;
        float* ob = out + (size_t)b * kC * kNVOX + seg;
        const float* f = fv + (size_t)b * kC * kN + n;
#pragma unroll
        for (int c = 0; c < kC; ++c)
            atomicAdd(ob + (size_t)c * kNVOX, f[(size_t)c * kN]);
        atomicAdd(&g_cnt[(size_t)b * kNVOX + seg], 1.0f);
        return;
    }

    // ---- role: 3-NN (packed f32x2 distance math) ----
    __shared__ float4 spA[PAIRS];  // (x0,x1,y0,y1) per candidate pair
    __shared__ float4 spB[PAIRS];  // (z0,z1,q0,q1)

    const int b    = blockIdx.x / NNB_PER_B;
    const int fb   = blockIdx.x % NNB_PER_B;
    const int base = fb * 16;
    const int fcnt = g_fcnt[b];
    if (base >= fcnt) return;                    // uniform block exit

    const int lane = threadIdx.x & 31;
    const int w    = threadIdx.x >> 5;
    const int rA   = base + 2 * w;
    const int rB   = rA + 1;
    const bool activeA = (rA < fcnt);
    const bool activeB = (rB < fcnt);

    float4 fpA = g_far[(size_t)b * kN + (activeA ? rA : 0)];
    float4 fpB = g_far[(size_t)b * kN + (activeB ? rB : 0)];
    const unsigned long long aX2 = pack2(-2.0f * fpA.x, -2.0f * fpA.x);
    const unsigned long long aY2 = pack2(-2.0f * fpA.y, -2.0f * fpA.y);
    const unsigned long long aZ2 = pack2(-2.0f * fpA.z, -2.0f * fpA.z);
    const unsigned long long bX2 = pack2(-2.0f * fpB.x, -2.0f * fpB.x);
    const unsigned long long bY2 = pack2(-2.0f * fpB.y, -2.0f * fpB.y);
    const unsigned long long bZ2 = pack2(-2.0f * fpB.z, -2.0f * fpB.z);

    const int V = g_ncnt[b];
    const float4* __restrict__ vp = &g_near[(size_t)b * kN];

    float lA0 = CUDART_INF_F, lA1 = CUDART_INF_F, lA2 = CUDART_INF_F;
    int   vA0 = 0x7FFFFFFF,   vA1 = 0x7FFFFFFF,   vA2 = 0x7FFFFFFF;
    float lB0 = CUDART_INF_F, lB1 = CUDART_INF_F, lB2 = CUDART_INF_F;
    int   vB0 = 0x7FFFFFFF,   vB1 = 0x7FFFFFFF,   vB2 = 0x7FFFFFFF;
    float TmA = activeA ? CUDART_INF_F : -CUDART_INF_F;
    float TmB = activeB ? CUDART_INF_F : -CUDART_INF_F;

    const ulonglong2* __restrict__ pA = reinterpret_cast<const ulonglong2*>(spA);
    const ulonglong2* __restrict__ pB = reinterpret_cast<const ulonglong2*>(spB);

    int it = 0;
    for (int start = 0; start < V; start += TILE) {
        int len = V - start; len = (len > TILE) ? TILE : len;
        int npair = (len + 1) >> 1;
        int Ppad = (npair + 63) & ~63;
        for (int i = threadIdx.x; i < Ppad; i += 256) {
            int c0 = start + 2 * i;
            bool ok0 = (2 * i < len), ok1 = (2 * i + 1 < len);
            float4 P0 = ok0 ? vp[c0] : make_float4(0.f, 0.f, 0.f, 0.f);
            float4 P1 = ok1 ? vp[c0 + 1] : make_float4(0.f, 0.f, 0.f, 0.f);
            float q0 = ok0 ? fmaf(P0.x, P0.x, fmaf(P0.y, P0.y, P0.z * P0.z))
                           : CUDART_INF_F;
            float q1 = ok1 ? fmaf(P1.x, P1.x, fmaf(P1.y, P1.y, P1.z * P1.z))
                           : CUDART_INF_F;
            spA[i] = make_float4(P0.x, P1.x, P0.y, P1.y);
            spB[i] = make_float4(P0.z, P1.z, q0, q1);
        }
        __syncthreads();

        for (int k = 0; k < Ppad; k += 64, ++it) {
            int u0 = k + lane, u1 = u0 + 32;
            ulonglong2 a0 = pA[u0], b0 = pB[u0];   // pair: cands 2u0, 2u0+1
            ulonglong2 a1 = pA[u1], b1 = pB[u1];
            // packed dd' = q - 2 p.f for 2 cands at once
            unsigned long long dA0 = fma2(a0.x, aX2, fma2(a0.y, aY2, fma2(b0.x, aZ2, b0.y)));
            unsigned long long dA1 = fma2(a1.x, aX2, fma2(a1.y, aY2, fma2(b1.x, aZ2, b1.y)));
            unsigned long long dB0 = fma2(a0.x, bX2, fma2(a0.y, bY2, fma2(b0.x, bZ2, b0.y)));
            unsigned long long dB1 = fma2(a1.x, bX2, fma2(a1.y, bY2, fma2(b1.x, bZ2, b1.y)));
            float fA00, fA01, fA10, fA11, fB00, fB01, fB10, fB11;
            unpack2(dA0, fA00, fA01);
            unpack2(dA1, fA10, fA11);
            unpack2(dB0, fB00, fB01);
            unpack2(dB1, fB10, fB11);
            float mnA = fminf(fminf(fA00, fA01), fminf(fA10, fA11));
            float mnB = fminf(fminf(fB00, fB01), fminf(fB10, fB11));
            int c0 = start + 2 * u0;
            int c1 = start + 2 * u1;
            if (mnA < TmA) {
                insert3v(fA00, c0,     lA0, lA1, lA2, vA0, vA1, vA2);
                insert3v(fA01, c0 + 1, lA0, lA1, lA2, vA0, vA1, vA2);
                insert3v(fA10, c1,     lA0, lA1, lA2, vA0, vA1, vA2);
                insert3v(fA11, c1 + 1, lA0, lA1, lA2, vA0, vA1, vA2);
            }
            if (mnB < TmB) {
                insert3v(fB00, c0,     lB0, lB1, lB2, vB0, vB1, vB2);
                insert3v(fB01, c0 + 1, lB0, lB1, lB2, vB0, vB1, vB2);
                insert3v(fB10, c1,     lB0, lB1, lB2, vB0, vB1, vB2);
                insert3v(fB11, c1 + 1, lB0, lB1, lB2, vB0, vB1, vB2);
            }
            if ((it & 3) == 3) {  // refresh conservative thresholds (stale=safe)
                if (activeA) TmA = warpmin(lA2);
                if (activeB) TmB = warpmin(lB2);
            }
        }
        __syncthreads();
    }

    float rdA[3], rdB[3];
    int riA[3], riB[3];
    merge32(lA0, lA1, lA2, vA0, vA1, vA2, rdA, riA);
    merge32(lB0, lB1, lB2, vB0, vB1, vB2, rdB, riB);

    const bool isA = lane < 16;
    const int lh = lane & 15;
    const bool act = isA ? activeA : activeB;
    if (!act) return;

    float fx = isA ? fpA.x : fpB.x;
    float fy = isA ? fpA.y : fpB.y;
    float fz = isA ? fpA.z : fpB.z;

    float rd[3];
    int u[3];
#pragma unroll
    for (int k = 0; k < 3; ++k) {
        int r = isA ? riA[k] : riB[k];
        if ((unsigned)r < (unsigned)kN) {
            float4 p = vp[r];
            float dx = p.x - fx, dy = p.y - fy, dz = p.z - fz;
            rd[k] = fmaf(dx, dx, fmaf(dy, dy, dz * dz));
            u[k] = __float_as_int(p.w);
        } else {
            rd[k] = CUDART_INF_F;
            u[k] = 0;
        }
    }

    float w0 = 1.0f / (rd[0] + 1e-8f);
    float w1 = 1.0f / (rd[1] + 1e-8f);
    float w2 = 1.0f / (rd[2] + 1e-8f);
    float ws = w0 + w1 + w2;
    w0 /= ws; w1 /= ws; w2 /= ws;

    int ix = (int)floorf((fx - PCR0) / VOXS);
    int iy = (int)floorf((fy - PCR1) / VOXS);
    bool inb = ix >= 0 && ix < kNX && iy >= 0 && iy < kNY &&
               fz >= PCR2 && fz < PCR5;
    if (!inb) return;
    int seg = iy * kNX + ix;

    const float* fb_ = fv + (size_t)b * kC * kN;
    float* ob = out + (size_t)b * kC * kNVOX;
#pragma unroll
    for (int k = 0; k < 2; ++k) {
        int c = lh + 16 * k;
        const float* fc = fb_ + (size_t)c * kN;
        float val = w0 * fc[u[0]] + w1 * fc[u[1]] + w2 * fc[u[2]];
        atomicAdd(ob + (size_t)c * kNVOX + seg, val);
    }
    if (lh == 0) atomicAdd(&g_cnt[(size_t)b * kNVOX + seg], 1.0f);
}

// ---------------------------------------------------------------------------
// 3) sparse finalize: divide only voxels with count > 1 (identity otherwise)
// ---------------------------------------------------------------------------
__global__ void k_fin(float* __restrict__ out) {
    int i = blockIdx.x * blockDim.x + threadIdx.x;
    if (i >= kB * kNVOX) return;
    int b = i / kNVOX, v = i % kNVOX;
    float c = g_cnt[i];
    if (c > 1.0f) {
        float inv = 1.0f / c;
        float* ob = out + (size_t)b * kC * kNVOX + v;
#pragma unroll
        for (int ch = 0; ch < kC; ++ch) ob[(size_t)ch * kNVOX] *= inv;
    }
}

// ---------------------------------------------------------------------------
extern "C" void kernel_launch(void* const* d_in, const int* in_sizes, int n_in,
                              void* d_out, int out_size) {
    const float* fv   = (const float*)d_in[0];  // (B,C,H,W)
    const float* pts  = (const float*)d_in[1];  // (B,4,H,W)
    const float* ptsf = (const float*)d_in[2];  // (B,4,H,W)
    const int*   m    = (const int*)d_in[3];    // (B,H,W)
    const int*   mf   = (const int*)d_in[4];    // (B,H,W)
    float* out = (float*)d_out;                 // (B,C,NY,NX)

    k_init<<<4 + ZB, 1024>>>((float4*)out, pts, ptsf, m, mf);
    k_main<<<kB * NNB_PER_B + (kB * kN) / 256, 256>>>(fv, pts, m, out);
    k_fin<<<(kB * kNVOX + 255) / 256, 256>>>(out);
}